// round 1
// baseline (speedup 1.0000x reference)
#include <cuda_runtime.h>
#include <cstdint>

// Problem constants (from setup_inputs): N=100000, E=1600000, D=8, K=1, C=32.
// Buffers sized with headroom; dims taken from in_sizes at runtime.
#define MAXN 100352

__device__ __align__(16) float g_xg[MAXN * 32];     // x @ g
__device__ __align__(16) float g_rootb[MAXN * 32];  // x @ root + bias
__device__ __align__(16) float g_agg[MAXN * 32];    // scatter accumulator
__device__ __align__(16) float g_h[MAXN * 32];      // layer-1 output
__device__ float g_cnt[MAXN];                        // in-degree

// Fused: xg = x @ g ; rootb = x @ root + bias.  8 rows per 256-thread block.
__global__ void gemm_xform(const float* __restrict__ x,
                           const float* __restrict__ g,
                           const float* __restrict__ root,
                           const float* __restrict__ bias,
                           float* __restrict__ xg,
                           float* __restrict__ rootb,
                           int N) {
    __shared__ float sg[1024];
    __shared__ float sr[1024];
    __shared__ float sb[32];
    __shared__ float sx[8][33];

    int t = threadIdx.x;  // 256 threads
    for (int i = t; i < 1024; i += 256) { sg[i] = g[i]; sr[i] = root[i]; }
    if (t < 32) sb[t] = bias[t];

    int r = t >> 5;       // row within block (0..7)
    int c = t & 31;       // column (0..31)
    int row = blockIdx.x * 8 + r;
    if (row < N) sx[r][c] = x[row * 32 + c];
    __syncthreads();
    if (row >= N) return;

    float a = 0.f, b = 0.f;
#pragma unroll
    for (int k = 0; k < 32; k++) {
        float xv = sx[r][k];
        a = fmaf(xv, sg[k * 32 + c], a);
        b = fmaf(xv, sr[k * 32 + c], b);
    }
    xg[row * 32 + c] = a;
    rootb[row * 32 + c] = b + sb[c];
}

// Edge pass: 8 lanes per edge. Lane l owns pseudo-coord dim l (for the Gaussian)
// and channels [4l, 4l+4) as one float4. Gather is one coalesced 128B line per
// edge; scatter is red.global.add.v4.f32 (8 vector atomics per edge).
__global__ void edge_pass(const int* __restrict__ ei,      // [2, E] (src row 0, dst row 1)
                          const float* __restrict__ ea,    // [E, 8]
                          const float* __restrict__ mu,    // [1, 8]
                          const float* __restrict__ sigma, // [1, 8]
                          const float4* __restrict__ xg,   // [N, 8] float4
                          float* __restrict__ agg,         // [N, 32]
                          float* __restrict__ cnt,         // [N]
                          int E, int do_cnt) {
    long long idx = (long long)blockIdx.x * blockDim.x + threadIdx.x;
    int e = (int)(idx >> 3);
    int l = (int)(idx & 7);
    if (e >= E) return;

    float m = mu[l];
    float s = sigma[l];
    float d = ea[e * 8 + l] - m;
    float t = (-0.5f * d * d) / (1e-15f + s * s);
    // reduce over the 8 pseudo-coord dims (lane groups of 8 align inside warp)
    t += __shfl_xor_sync(0xffffffffu, t, 1);
    t += __shfl_xor_sync(0xffffffffu, t, 2);
    t += __shfl_xor_sync(0xffffffffu, t, 4);
    float gau = __expf(t);

    int src = ei[e];
    int dst = ei[E + e];

    float4 v = xg[src * 8 + l];
    v.x *= gau; v.y *= gau; v.z *= gau; v.w *= gau;

    float* p = agg + (size_t)dst * 32 + l * 4;
    asm volatile("red.global.add.v4.f32 [%0], {%1,%2,%3,%4};"
                 :: "l"(p), "f"(v.x), "f"(v.y), "f"(v.z), "f"(v.w)
                 : "memory");

    if (do_cnt && l == 0) atomicAdd(cnt + dst, 1.0f);
}

// out = agg / max(cnt, 1) + rootb   (vectorized float4)
__global__ void finalize4(const float4* __restrict__ agg,
                          const float4* __restrict__ rootb,
                          const float* __restrict__ cnt,
                          float4* __restrict__ out,
                          int N) {
    int i = blockIdx.x * blockDim.x + threadIdx.x;  // over N*8 float4s
    if (i >= N * 8) return;
    int n = i >> 3;
    float rinv = 1.0f / fmaxf(cnt[n], 1.0f);
    float4 a = agg[i];
    float4 r = rootb[i];
    a.x = a.x * rinv + r.x;
    a.y = a.y * rinv + r.y;
    a.z = a.z * rinv + r.z;
    a.w = a.w * rinv + r.w;
    out[i] = a;
}

extern "C" void kernel_launch(void* const* d_in, const int* in_sizes, int n_in,
                              void* d_out, int out_size) {
    const int*   ei  = (const int*)d_in[0];
    const float* ew  = (const float*)d_in[1];
    const float* x   = (const float*)d_in[2];
    const float* g1  = (const float*)d_in[3];
    const float* mu1 = (const float*)d_in[4];
    const float* s1  = (const float*)d_in[5];
    const float* r1  = (const float*)d_in[6];
    const float* b1  = (const float*)d_in[7];
    const float* g2  = (const float*)d_in[8];
    const float* mu2 = (const float*)d_in[9];
    const float* s2  = (const float*)d_in[10];
    const float* r2  = (const float*)d_in[11];
    const float* b2  = (const float*)d_in[12];

    const int E = in_sizes[0] / 2;
    const int N = in_sizes[2] / 32;

    float *xg, *rootb, *agg, *h, *cnt;
    cudaGetSymbolAddress((void**)&xg, g_xg);
    cudaGetSymbolAddress((void**)&rootb, g_rootb);
    cudaGetSymbolAddress((void**)&agg, g_agg);
    cudaGetSymbolAddress((void**)&h, g_h);
    cudaGetSymbolAddress((void**)&cnt, g_cnt);

    const int gemm_blocks = (N + 7) / 8;
    const int edge_blocks = (int)(((long long)E * 8 + 255) / 256);
    const int fin_blocks  = (N * 8 + 255) / 256;

    // ---- layer 1 ----
    cudaMemsetAsync(agg, 0, (size_t)N * 32 * sizeof(float), 0);
    cudaMemsetAsync(cnt, 0, (size_t)N * sizeof(float), 0);
    gemm_xform<<<gemm_blocks, 256>>>(x, g1, r1, b1, xg, rootb, N);
    edge_pass<<<edge_blocks, 256>>>(ei, ew, mu1, s1, (const float4*)xg, agg, cnt, E, 1);
    finalize4<<<fin_blocks, 256>>>((const float4*)agg, (const float4*)rootb, cnt, (float4*)h, N);

    // ---- layer 2 ----
    cudaMemsetAsync(agg, 0, (size_t)N * 32 * sizeof(float), 0);
    gemm_xform<<<gemm_blocks, 256>>>(h, g2, r2, b2, xg, rootb, N);
    edge_pass<<<edge_blocks, 256>>>(ei, ew, mu2, s2, (const float4*)xg, agg, cnt, E, 0);
    finalize4<<<fin_blocks, 256>>>((const float4*)agg, (const float4*)rootb, cnt, (float4*)d_out, N);
}

// round 2
// speedup vs baseline: 1.2039x; 1.2039x over previous
#include <cuda_runtime.h>
#include <cstdint>

// N=100000, E=1600000, D=8, K=1, C=32 (dims read from in_sizes at runtime).
#define MAXN 100352

__device__ __align__(16) float g_xg[MAXN * 32];     // x @ g
__device__ __align__(16) float g_rootb[MAXN * 32];  // x @ root + bias (layer 1)
__device__ __align__(16) float g_rootb2[MAXN * 32]; // layer 2 root term
__device__ __align__(16) float g_agg[MAXN * 32];    // scatter accumulator
__device__ float g_cnt[MAXN];                        // in-degree

// Register-weight GEMM. Each lane owns one output column of g AND one of root
// (64 weight registers). 128-row tile in shared; x values broadcast via LDS.
// FUSE=true: input row = agg[row]/max(cnt,1) + rb_in[row]  (finalize of the
// previous layer fused into the tile-staging loads).
template <bool FUSE>
__global__ void __launch_bounds__(256) gemm_k(
    const float* __restrict__ xin,    // x (FUSE=false) or agg (FUSE=true)
    const float* __restrict__ cnt,    // FUSE only
    const float* __restrict__ rb_in,  // FUSE only
    const float* __restrict__ g,      // [32,32]
    const float* __restrict__ root,   // [32,32]
    const float* __restrict__ bias,   // [32]
    float* __restrict__ xg,
    float* __restrict__ rb_out,
    int N) {
    __shared__ float sx[128][32];
    const int t = threadIdx.x;
    const int lane = t & 31;
    const int w = t >> 5;  // 8 warps

    float wg[32], wr[32];
#pragma unroll
    for (int k = 0; k < 32; k++) {
        wg[k] = __ldg(g + k * 32 + lane);
        wr[k] = __ldg(root + k * 32 + lane);
    }
    const float bv = __ldg(bias + lane);

    const int base = blockIdx.x * 128;
    const int nrows = min(128, N - base);

    if (FUSE) {
        for (int i = t; i < nrows * 32; i += 256) {
            int r = i >> 5, c = i & 31;
            int row = base + r;
            float rinv = 1.0f / fmaxf(__ldg(cnt + row), 1.0f);
            sx[r][c] = xin[(size_t)row * 32 + c] * rinv + rb_in[(size_t)row * 32 + c];
        }
    } else {
        for (int i = t; i < nrows * 32; i += 256)
            sx[i >> 5][i & 31] = xin[(size_t)base * 32 + i];
    }
    __syncthreads();

    for (int r = w; r < nrows; r += 8) {
        float a = 0.0f, b = bv;
#pragma unroll
        for (int k = 0; k < 32; k++) {
            float xv = sx[r][k];   // broadcast LDS (all lanes same addr)
            a = fmaf(xv, wg[k], a);
            b = fmaf(xv, wr[k], b);
        }
        size_t o = (size_t)(base + r) * 32 + lane;
        xg[o] = a;
        rb_out[o] = b;
    }
}

// Edge pass: 8 lanes per edge. Lane l owns pseudo-coord dim l and channels
// [4l,4l+4) as one float4. Gather = one coalesced 128B line per edge;
// scatter = red.global.add.v4.f32.
__global__ void __launch_bounds__(256) edge_pass(
    const int* __restrict__ ei,      // [2, E]
    const float* __restrict__ ea,    // [E, 8]
    const float* __restrict__ mu,    // [1, 8]
    const float* __restrict__ sigma, // [1, 8]
    const float4* __restrict__ xg,   // [N, 8] float4
    float* __restrict__ agg,         // [N, 32]
    float* __restrict__ cnt,         // [N]
    int E, int do_cnt) {
    long long idx = (long long)blockIdx.x * blockDim.x + threadIdx.x;
    int e = (int)(idx >> 3);
    int l = (int)(idx & 7);
    if (e >= E) return;

    float m = __ldg(mu + l);
    float s = __ldg(sigma + l);
    float d = ea[e * 8 + l] - m;
    float t = (-0.5f * d * d) / (1e-15f + s * s);
    t += __shfl_xor_sync(0xffffffffu, t, 1);
    t += __shfl_xor_sync(0xffffffffu, t, 2);
    t += __shfl_xor_sync(0xffffffffu, t, 4);
    float gau = __expf(t);

    int src = __ldg(ei + e);
    int dst = __ldg(ei + E + e);

    float4 v = xg[(size_t)src * 8 + l];
    v.x *= gau; v.y *= gau; v.z *= gau; v.w *= gau;

    float* p = agg + (size_t)dst * 32 + l * 4;
    asm volatile("red.global.add.v4.f32 [%0], {%1,%2,%3,%4};"
                 :: "l"(p), "f"(v.x), "f"(v.y), "f"(v.z), "f"(v.w)
                 : "memory");

    if (do_cnt && l == 0) atomicAdd(cnt + dst, 1.0f);
}

// out = agg / max(cnt,1) + rootb   (final layer only)
__global__ void __launch_bounds__(256) finalize4(
    const float4* __restrict__ agg,
    const float4* __restrict__ rootb,
    const float* __restrict__ cnt,
    float4* __restrict__ out,
    int N) {
    int i = blockIdx.x * blockDim.x + threadIdx.x;
    if (i >= N * 8) return;
    int n = i >> 3;
    float rinv = 1.0f / fmaxf(__ldg(cnt + n), 1.0f);
    float4 a = agg[i];
    float4 r = rootb[i];
    a.x = a.x * rinv + r.x;
    a.y = a.y * rinv + r.y;
    a.z = a.z * rinv + r.z;
    a.w = a.w * rinv + r.w;
    out[i] = a;
}

extern "C" void kernel_launch(void* const* d_in, const int* in_sizes, int n_in,
                              void* d_out, int out_size) {
    const int*   ei  = (const int*)d_in[0];
    const float* ew  = (const float*)d_in[1];
    const float* x   = (const float*)d_in[2];
    const float* g1  = (const float*)d_in[3];
    const float* mu1 = (const float*)d_in[4];
    const float* s1  = (const float*)d_in[5];
    const float* r1  = (const float*)d_in[6];
    const float* b1  = (const float*)d_in[7];
    const float* g2  = (const float*)d_in[8];
    const float* mu2 = (const float*)d_in[9];
    const float* s2  = (const float*)d_in[10];
    const float* r2  = (const float*)d_in[11];
    const float* b2  = (const float*)d_in[12];

    const int E = in_sizes[0] / 2;
    const int N = in_sizes[2] / 32;

    float *xg, *rootb, *rootb2, *agg, *cnt;
    cudaGetSymbolAddress((void**)&xg, g_xg);
    cudaGetSymbolAddress((void**)&rootb, g_rootb);
    cudaGetSymbolAddress((void**)&rootb2, g_rootb2);
    cudaGetSymbolAddress((void**)&agg, g_agg);
    cudaGetSymbolAddress((void**)&cnt, g_cnt);

    const int gemm_blocks = (N + 127) / 128;
    const int edge_blocks = (int)(((long long)E * 8 + 255) / 256);
    const int fin_blocks  = (N * 8 + 255) / 256;

    // ---- layer 1 ----
    cudaMemsetAsync(agg, 0, (size_t)N * 32 * sizeof(float), 0);
    cudaMemsetAsync(cnt, 0, (size_t)N * sizeof(float), 0);
    gemm_k<false><<<gemm_blocks, 256>>>(x, nullptr, nullptr, g1, r1, b1, xg, rootb, N);
    edge_pass<<<edge_blocks, 256>>>(ei, ew, mu1, s1, (const float4*)xg, agg, cnt, E, 1);

    // ---- layer 2 (finalize of layer 1 fused into the GEMM tile load) ----
    gemm_k<true><<<gemm_blocks, 256>>>(agg, cnt, rootb, g2, r2, b2, xg, rootb2, N);
    cudaMemsetAsync(agg, 0, (size_t)N * 32 * sizeof(float), 0);
    edge_pass<<<edge_blocks, 256>>>(ei, ew, mu2, s2, (const float4*)xg, agg, cnt, E, 0);
    finalize4<<<fin_blocks, 256>>>((const float4*)agg, (const float4*)rootb2, cnt, (float4*)d_out, N);
}